// round 2
// baseline (speedup 1.0000x reference)
#include <cuda_runtime.h>
#include <cstdint>

// Problem constants (fixed by the dataset)
#define NN      100000
#define EE      3200000
#define F_IN    256
#define RR      16
#define DD      128
#define BB      16384
#define EPS     1e-5f

// ---------------- scratch (no allocs allowed) ----------------
__device__ __align__(16) float g_h   [NN * RR];   // x @ W^T
__device__ __align__(16) float g_hagg[NN * RR];   // aggregated GCN output
__device__ float g_deg [NN];
__device__ float g_dinv[NN];
__device__ float g_stats[2];                      // sum, sumsq

// ---------------- helpers ----------------
__device__ __forceinline__ float warpsum(float v) {
#pragma unroll
    for (int o = 16; o > 0; o >>= 1) v += __shfl_xor_sync(0xFFFFFFFFu, v, o);
    return v;
}

__device__ __forceinline__ void red4(float* p, float a, float b, float c, float d) {
    asm volatile("red.global.add.v4.f32 [%0], {%1,%2,%3,%4};"
                 :: "l"(p), "f"(a), "f"(b), "f"(c), "f"(d) : "memory");
}

// ---------------- kernels ----------------

// 0) init: deg = 1.0 (self loop), stats = 0
__global__ void k_init() {
    int i = blockIdx.x * blockDim.x + threadIdx.x;
    if (i < NN) g_deg[i] = 1.0f;
    if (i < 2)  g_stats[i] = 0.0f;
}

// 1) degree: atomic count of incoming edges at dst
__global__ void k_deg(const int* __restrict__ ei) {
    int e = blockIdx.x * blockDim.x + threadIdx.x;
    if (e < EE) {
        int dst = ei[EE + e];
        atomicAdd(&g_deg[dst], 1.0f);
    }
}

// 2) h = x @ W^T   (one warp per node, W cached in smem)
__global__ void k_lin(const float* __restrict__ x, const float* __restrict__ W) {
    __shared__ float4 Ws[RR * 64];                 // 16 rows x 64 float4 = 16KB
    for (int i = threadIdx.x; i < RR * 64; i += blockDim.x)
        Ws[i] = ((const float4*)W)[i];
    __syncthreads();

    int gwarp  = (blockIdx.x * blockDim.x + threadIdx.x) >> 5;
    int lane   = threadIdx.x & 31;
    int nwarps = (gridDim.x * blockDim.x) >> 5;

    for (int n = gwarp; n < NN; n += nwarps) {
        const float4* xr = (const float4*)(x + (size_t)n * F_IN);
        float4 x0 = xr[lane], x1 = xr[lane + 32];
        float myval = 0.0f;
#pragma unroll
        for (int r = 0; r < RR; r++) {
            float4 w0 = Ws[r * 64 + lane], w1 = Ws[r * 64 + lane + 32];
            float acc = x0.x*w0.x + x0.y*w0.y + x0.z*w0.z + x0.w*w0.w
                      + x1.x*w1.x + x1.y*w1.y + x1.z*w1.z + x1.w*w1.w;
            acc = warpsum(acc);
            if (lane == r) myval = acc;
        }
        if (lane < RR) g_h[(size_t)n * RR + lane] = myval;
    }
}

// 3) dinv + self-loop init: hagg = h * dinv^2 + b
__global__ void k_self(const float* __restrict__ bias) {
    int t = blockIdx.x * blockDim.x + threadIdx.x;
    if (t < NN * RR) {
        int n = t >> 4, r = t & 15;
        float dg = g_deg[n];
        float d  = dg > 0.0f ? rsqrtf(dg) : 0.0f;
        if (r == 0) g_dinv[n] = d;
        g_hagg[t] = g_h[t] * d * d + bias[r];
    }
}

// 4) edge aggregation: hagg[dst] += h[src] * dinv[src]*dinv[dst]
__global__ void k_edges(const int* __restrict__ ei) {
    int e = blockIdx.x * blockDim.x + threadIdx.x;
    if (e >= EE) return;
    int s = ei[e];
    int d = ei[EE + e];
    float w = g_dinv[s] * g_dinv[d];

    const float4* hs = (const float4*)(g_h + (size_t)s * RR);
    float4 a0 = hs[0], a1 = hs[1], a2 = hs[2], a3 = hs[3];
    float* dp = g_hagg + (size_t)d * RR;
    red4(dp,      a0.x*w, a0.y*w, a0.z*w, a0.w*w);
    red4(dp + 4,  a1.x*w, a1.y*w, a1.z*w, a1.w*w);
    red4(dp + 8,  a2.x*w, a2.y*w, a2.z*w, a2.w*w);
    red4(dp + 12, a3.x*w, a3.y*w, a3.z*w, a3.w*w);
}

// 5) global LN stats: sum + sumsq over all NN*RR elements
__global__ void k_stats() {
    const float4* p = (const float4*)g_hagg;
    const int total = NN * RR / 4;
    float s = 0.0f, q = 0.0f;
    for (int i = blockIdx.x * blockDim.x + threadIdx.x; i < total;
         i += gridDim.x * blockDim.x) {
        float4 v = p[i];
        s += v.x + v.y + v.z + v.w;
        q += v.x*v.x + v.y*v.y + v.z*v.z + v.w*v.w;
    }
    s = warpsum(s); q = warpsum(q);
    __shared__ float ss[32], qq[32];
    int lane = threadIdx.x & 31, wid = threadIdx.x >> 5;
    if (lane == 0) { ss[wid] = s; qq[wid] = q; }
    __syncthreads();
    if (wid == 0) {
        int nw = blockDim.x >> 5;
        s = lane < nw ? ss[lane] : 0.0f;
        q = lane < nw ? qq[lane] : 0.0f;
        s = warpsum(s); q = warpsum(q);
        if (lane == 0) { atomicAdd(&g_stats[0], s); atomicAdd(&g_stats[1], q); }
    }
}

// 6) output: per batch row, LN + PReLU + @trans. 8 rows per 128-thread block.
__global__ void k_out(const float* __restrict__ trans,
                      const int* __restrict__ batch,
                      const float* __restrict__ lnw,
                      const float* __restrict__ lnb,
                      const float* __restrict__ pa,
                      float* __restrict__ out) {
    __shared__ float ts[RR * DD];                  // 8KB
    __shared__ float hv[8][RR];
    for (int i = threadIdx.x; i < RR * DD; i += blockDim.x)
        ts[i] = trans[i];

    const float inv = 1.0f / (float)(NN * RR);
    float mean = g_stats[0] * inv;
    float var  = g_stats[1] * inv - mean * mean;
    float rinv = rsqrtf(var + EPS);
    float a    = pa[0];

    int row0 = blockIdx.x * 8;
    {   // 128 threads = 8 rows x 16 channels, exactly
        int row = threadIdx.x >> 4, r = threadIdx.x & 15;
        int bi = batch[row0 + row];
        float v = g_hagg[(size_t)bi * RR + r];
        v = (v - mean) * rinv * lnw[r] + lnb[r];
        v = v >= 0.0f ? v : a * v;
        hv[row][r] = v;
    }
    __syncthreads();

#pragma unroll
    for (int row = 0; row < 8; row++) {
        float acc = 0.0f;
#pragma unroll
        for (int k = 0; k < RR; k++)
            acc += hv[row][k] * ts[k * DD + threadIdx.x];
        out[(size_t)(row0 + row) * DD + threadIdx.x] = acc;
    }
}

// ---------------- launch ----------------
extern "C" void kernel_launch(void* const* d_in, const int* in_sizes, int n_in,
                              void* d_out, int out_size) {
    const float* x     = (const float*)d_in[0];
    const int*   ei    = (const int*)d_in[1];
    const float* trans = (const float*)d_in[2];
    const int*   batch = (const int*)d_in[3];
    const float* W     = (const float*)d_in[4];
    const float* bias  = (const float*)d_in[5];
    const float* lnw   = (const float*)d_in[6];
    const float* lnb   = (const float*)d_in[7];
    const float* pa    = (const float*)d_in[8];
    float* out = (float*)d_out;

    k_init <<<(NN + 255) / 256, 256>>>();
    k_deg  <<<(EE + 255) / 256, 256>>>(ei);
    k_lin  <<<(NN + 7) / 8, 256>>>(x, W);         // 8 warps/block, 1 node/warp
    k_self <<<(NN * RR + 255) / 256, 256>>>(bias);
    k_edges<<<(EE + 255) / 256, 256>>>(ei);
    k_stats<<<1024, 256>>>();
    k_out  <<<BB / 8, 128>>>(trans, batch, lnw, lnb, pa, out);
}